// round 10
// baseline (speedup 1.0000x reference)
#include <cuda_runtime.h>
#include <cstdint>

#define NROWS 32768
#define KCODES 8192
#define DD 256
#define QSIZE (NROWS * DD)

#define MT 128                  // rows per unit
#define NSEG 2048               // codes per unit
#define NUNITS ((NROWS / MT) * (KCODES / NSEG))   // 1024
#define NTPU (NSEG / 128)       // 16 n-tiles (128 codes) per unit
#define NCH (NTPU * 8)          // 128 B-chunks (32 k x 128 codes) per unit

#define NTHR 512

// smem: A image 131072 B, then 4 B-chunk buffers of 16384 B
#define SMB_B0 131072
#define SM_TOTAL (131072 + 4 * 16384)   // 196608

// ---- device scratch ----
__device__ unsigned long long g_best[NROWS];
__device__ float g_zz[NROWS];
__device__ float g_ee[KCODES];
__device__ float g_partial[8192];
__device__ int   g_work;
__device__ float g_zT[NROWS * DD];      // per 128-row block: [k][swizzled m] image
__device__ float g_ebT[KCODES * DD];    // per (tile,kc) chunk: 4096-float smem image

#define DUPB(dst, s)  asm("mov.b64 %0, {%1, %1};" : "=l"(dst) : "f"(s))
#define FFMA2(acc, a, b) asm("fma.rn.f32x2 %0, %1, %2, %0;" : "+l"(acc) : "l"(a), "l"(b))
#define UNPK(lo, hi, v) asm("mov.b64 {%0, %1}, %2;" : "=f"(lo), "=f"(hi) : "l"(v))

__device__ __forceinline__ uint32_t smem_u32(const void* p) {
    uint32_t a;
    asm("{ .reg .u64 t; cvta.to.shared.u64 t, %1; cvt.u32.u64 %0, t; }" : "=r"(a) : "l"(p));
    return a;
}
#define CPASYNC16(dst, src) \
    asm volatile("cp.async.cg.shared.global [%0], [%1], 16;" :: "r"(dst), "l"(src))
#define CPCOMMIT() asm volatile("cp.async.commit_group;" ::: "memory")
#define CPWAIT2()  asm volatile("cp.async.wait_group 2;" ::: "memory")
#define CPWAIT1()  asm volatile("cp.async.wait_group 1;" ::: "memory")
#define CPWAIT0()  asm volatile("cp.async.wait_group 0;" ::: "memory")

// -------- init (graph-replayable) --------
__global__ void vq_init_kernel() {
    int i = blockIdx.x * 256 + threadIdx.x;
    g_best[i] = 0xFFFFFFFFFFFFFFFFULL;
    if (i == 0) g_work = 0;
}

// -------- exact row squared-norms (matched reference; unchanged) --------
__global__ void vq_norms_kernel(const float* __restrict__ src, float* __restrict__ dst,
                                int nrows) {
    int w = (blockIdx.x * blockDim.x + threadIdx.x) >> 5;
    int lane = threadIdx.x & 31;
    if (w >= nrows) return;
    const float* row = src + (size_t)w * DD;
    float s = 0.f;
#pragma unroll
    for (int j = 0; j < DD / 32; j++) {
        float v = row[lane + 32 * j];
        s = fmaf(v, v, s);
    }
#pragma unroll
    for (int o = 16; o; o >>= 1) s += __shfl_xor_sync(0xffffffffu, s, o);
    if (lane == 0) dst[w] = s;
}

// -------- prep: z -> transposed+swizzled block images (half-block per CTA) --------
__global__ void vq_prep_z(const float* __restrict__ z) {
    __shared__ alignas(16) float img[16384];   // 64 KB: 128 k x 128 m image half
    const int rb = blockIdx.x >> 1;
    const int h = blockIdx.x & 1;
    const int tid = threadIdx.x;
#pragma unroll
    for (int i = 0; i < 16; i++) {
        int f = tid + 256 * i;
        int m = f >> 5, k4l = f & 31;          // local k-group 0..31
        float4 v = *reinterpret_cast<const float4*>(
            z + ((size_t)(rb * 128 + m)) * DD + h * 128 + k4l * 4);
        int colg = (m >> 2) ^ (k4l & 7);       // (k4&7): h*32 is 0 mod 8
        float* p = img + (k4l * 4) * 128 + colg * 4 + (m & 3);
        p[0] = v.x; p[128] = v.y; p[256] = v.z; p[384] = v.w;
    }
    __syncthreads();
    float* dst = g_zT + (size_t)rb * 32768 + h * 16384;
#pragma unroll
    for (int i = 0; i < 16; i++) {
        int f = tid + 256 * i;
        *reinterpret_cast<float4*>(dst + f * 4) =
            *reinterpret_cast<const float4*>(img + f * 4);
    }
}

// -------- prep: codebook -> per-(tile,kc) 16KB chunk images --------
__global__ void vq_prep_cb(const float* __restrict__ cb) {
    __shared__ alignas(16) float img[4096];    // 16 KB
    const int tile = blockIdx.x >> 3;
    const int kc = blockIdx.x & 7;
    const int tid = threadIdx.x;
#pragma unroll
    for (int i = 0; i < 4; i++) {
        int f = tid + 256 * i;
        int n = f >> 3, bk4 = f & 7;
        float4 v = *reinterpret_cast<const float4*>(
            cb + ((size_t)(tile * 128 + n)) * DD + kc * 32 + bk4 * 4);
        int colg = (n >> 2) ^ bk4;
        float* p = img + (bk4 * 4) * 128 + colg * 4 + (n & 3);
        p[0] = v.x; p[128] = v.y; p[256] = v.z; p[384] = v.w;
    }
    __syncthreads();
    float* dst = g_ebT + ((size_t)tile * 8 + kc) * 4096;
#pragma unroll
    for (int i = 0; i < 4; i++) {
        int f = tid + 256 * i;
        *reinterpret_cast<float4*>(dst + f * 4) =
            *reinterpret_cast<const float4*>(img + f * 4);
    }
}

// -------- main exact FFMA2 distance-argmin: 512 threads, 4 warps/SMSP --------
// 512 thr = 32 tx (codes) x 16 ty (row-groups). Thread tile 8 rows x 4 codes.
// Warp = one ty -> A operand loads are warp-broadcast LDS.
__global__ void __launch_bounds__(NTHR, 1) vq_argmin_kernel() {
    extern __shared__ float smem[];
    float* At = smem;                          // 32768 floats (128 rows x 256 k image)
    __shared__ int s_u;
    const uint32_t sbase = smem_u32(smem);

    const int tid = threadIdx.x;
    const int tx = tid & 31;
    const int ty = tid >> 5;

    for (;;) {
        __syncthreads();                       // prior unit's smem reads done
        if (tid == 0) s_u = atomicAdd(&g_work, 1);
        __syncthreads();
        const int u = s_u;
        if (u >= NUNITS) return;
        const int rb = u & 255;
        const int cseg = u >> 8;
        const int row0 = rb * MT;
        const int cseg0 = cseg * NSEG;

        // issue A image (1 group) + first 3 B chunks (3 groups)
        {
            const float* asrc = g_zT + (size_t)rb * 32768;
#pragma unroll
            for (int i = 0; i < 16; i++) {
                int f = tid + NTHR * i;        // 8192 x 16B = 128 KB
                CPASYNC16(sbase + f * 16, asrc + f * 4);
            }
            CPCOMMIT();
#pragma unroll
            for (int c = 0; c < 3; c++) {
                const float* bsrc = g_ebT + ((size_t)(cseg * NTPU) * 8 + c) * 4096;
                uint32_t bb = sbase + SMB_B0 + c * 16384;
#pragma unroll
                for (int i = 0; i < 2; i++) {
                    int f = tid + NTHR * i;
                    CPASYNC16(bb + f * 16, bsrc + f * 4);
                }
                CPCOMMIT();
            }
        }

        float zzr[8], bd[8];
        int bk[8];
#pragma unroll
        for (int r = 0; r < 8; r++) {
            zzr[r] = g_zz[row0 + ty * 8 + r];
            bd[r] = __int_as_float(0x7f800000);
            bk[r] = 0;
        }

        unsigned long long acc[4][4];
        for (int ci = 0; ci < NCH; ci++) {
            const int kc = ci & 7;
            const int nt = ci >> 3;
            if (kc == 0) {
#pragma unroll
                for (int p = 0; p < 4; p++)
#pragma unroll
                    for (int c = 0; c < 4; c++) acc[p][c] = 0ULL;
            }

            if (ci < NCH - 2)       CPWAIT2(); // chunk ci resident
            else if (ci == NCH - 2) CPWAIT1();
            else                    CPWAIT0();
            __syncthreads();                   // visible to all; prior chunk reads done

            // issue chunk ci+3 into buf (ci+3)&3 (nobody reads it this iter)
            if (ci + 3 < NCH) {
                const int ci2 = ci + 3;
                const float* bsrc = g_ebT +
                    ((size_t)(cseg * NTPU + (ci2 >> 3)) * 8 + (ci2 & 7)) * 4096;
                uint32_t bb = sbase + SMB_B0 + (ci2 & 3) * 16384;
#pragma unroll
                for (int i = 0; i < 2; i++) {
                    int f = tid + NTHR * i;
                    CPASYNC16(bb + f * 16, bsrc + f * 4);
                }
                CPCOMMIT();
            }

            // ---- compute chunk ci: 32 k x (8 rows x 4 codes) per thread ----
            const float* Ac = At + kc * 4096;
            const float* Bc = smem + (SMB_B0 / 4) + (ci & 3) * 4096;
#pragma unroll 4
            for (int ks = 0; ks < 8; ks++) {
                const int oa0 = (((2 * ty)     ^ ks) << 2);
                const int oa1 = (((2 * ty + 1) ^ ks) << 2);
                const int ob0 = ((tx ^ ks) << 2);
                const float* Ak = Ac + ks * 512;
                const float* Bk = Bc + ks * 512;
#pragma unroll
                for (int j = 0; j < 4; j++) {
                    ulonglong2 a01 = *reinterpret_cast<const ulonglong2*>(Ak + j * 128 + oa0);
                    ulonglong2 a23 = *reinterpret_cast<const ulonglong2*>(Ak + j * 128 + oa1);
                    float4 b0 = *reinterpret_cast<const float4*>(Bk + j * 128 + ob0);

                    unsigned long long d0, d1, d2, d3;
                    DUPB(d0, b0.x); DUPB(d1, b0.y); DUPB(d2, b0.z); DUPB(d3, b0.w);

                    FFMA2(acc[0][0], a01.x, d0); FFMA2(acc[1][0], a01.y, d0);
                    FFMA2(acc[2][0], a23.x, d0); FFMA2(acc[3][0], a23.y, d0);
                    FFMA2(acc[0][1], a01.x, d1); FFMA2(acc[1][1], a01.y, d1);
                    FFMA2(acc[2][1], a23.x, d1); FFMA2(acc[3][1], a23.y, d1);
                    FFMA2(acc[0][2], a01.x, d2); FFMA2(acc[1][2], a01.y, d2);
                    FFMA2(acc[2][2], a23.x, d2); FFMA2(acc[3][2], a23.y, d2);
                    FFMA2(acc[0][3], a01.x, d3); FFMA2(acc[1][3], a01.y, d3);
                    FFMA2(acc[2][3], a23.x, d3); FFMA2(acc[3][3], a23.y, d3);
                }
            }

            // ---- epilogue per n-tile: d = (zz + ee) - 2*s, first-index argmin ----
            if (kc == 7) {
                const int cbase = cseg0 + nt * 128;
#pragma unroll
                for (int cc = 0; cc < 4; cc++) {
                    const int code = cbase + tx * 4 + cc;
                    const float ee = __ldg(&g_ee[code]);
#pragma unroll
                    for (int p = 0; p < 4; p++) {
                        float lo, hi;
                        UNPK(lo, hi, acc[p][cc]);
                        const float dlo = (zzr[2 * p]     + ee) - 2.0f * lo;
                        const float dhi = (zzr[2 * p + 1] + ee) - 2.0f * hi;
                        if (dlo < bd[2 * p])     { bd[2 * p] = dlo;     bk[2 * p] = code; }
                        if (dhi < bd[2 * p + 1]) { bd[2 * p + 1] = dhi; bk[2 * p + 1] = code; }
                    }
                }
            }
        }

        // ---- reduce across 32 tx lanes, then global atomic merge ----
#pragma unroll
        for (int r = 0; r < 8; r++) {
            float d = bd[r];
            int   k = bk[r];
#pragma unroll
            for (int o = 1; o < 32; o <<= 1) {
                float od = __shfl_xor_sync(0xffffffffu, d, o);
                int   ok = __shfl_xor_sync(0xffffffffu, k, o);
                if (od < d || (od == d && ok < k)) { d = od; k = ok; }
            }
            if (tx == 0) {
                unsigned long long key =
                    ((unsigned long long)__float_as_uint(d) << 32) | (unsigned int)k;
                atomicMin(&g_best[row0 + ty * 8 + r], key);
            }
        }
    }
}

// -------- output gather + straight-through + loss partials --------
__global__ void vq_output_kernel(const float* __restrict__ z, const float* __restrict__ cb,
                                 float* __restrict__ out) {
    const int tid = threadIdx.x;
    const size_t g4 = (size_t)blockIdx.x * 256 + tid;
    const int row = (int)(g4 >> 6);
    const int c4 = (int)(g4 & 63);
    const int idx = (int)(g_best[row] & 0xFFFFFFFFULL);

    const float4 zv = reinterpret_cast<const float4*>(z)[g4];
    const float4 qv = reinterpret_cast<const float4*>(cb)[(size_t)idx * 64 + c4];

    float4 o;
    o.x = zv.x + (qv.x - zv.x);
    o.y = zv.y + (qv.y - zv.y);
    o.z = zv.z + (qv.z - zv.z);
    o.w = zv.w + (qv.w - zv.w);
    reinterpret_cast<float4*>(out)[g4] = o;

    const float dx = zv.x - qv.x, dy = zv.y - qv.y, dz = zv.z - qv.z, dw = zv.w - qv.w;
    float part = dx * dx;
    part = fmaf(dy, dy, part);
    part = fmaf(dz, dz, part);
    part = fmaf(dw, dw, part);

    __shared__ float sp[256];
    sp[tid] = part;
    __syncthreads();
#pragma unroll
    for (int s = 128; s; s >>= 1) {
        if (tid < s) sp[tid] += sp[tid + s];
        __syncthreads();
    }
    if (tid == 0) g_partial[blockIdx.x] = sp[0];
}

// -------- deterministic final loss reduction --------
__global__ void vq_loss_kernel(float* __restrict__ out, int out_size) {
    __shared__ double sm[256];
    const int tid = threadIdx.x;
    double s = 0.0;
    for (int i = tid; i < 8192; i += 256) s += (double)g_partial[i];
    sm[tid] = s;
    __syncthreads();
#pragma unroll
    for (int st = 128; st; st >>= 1) {
        if (tid < st) sm[tid] += sm[tid + st];
        __syncthreads();
    }
    if (tid == 0) {
        const float m = (float)(sm[0] / (double)QSIZE);
        const float vq = 0.25f * m + m;
        for (int i = QSIZE; i < out_size; i++) out[i] = vq;
    }
}

extern "C" void kernel_launch(void* const* d_in, const int* in_sizes, int n_in,
                              void* d_out, int out_size) {
    const float* z  = (const float*)d_in[0];
    const float* cb = (const float*)d_in[1];
    if (n_in >= 2 && in_sizes[0] == KCODES * DD && in_sizes[1] == NROWS * DD) {
        const float* t = z; z = cb; cb = t;
    }
    float* out = (float*)d_out;

    cudaFuncSetAttribute(vq_argmin_kernel,
                         cudaFuncAttributeMaxDynamicSharedMemorySize, SM_TOTAL);

    float* zz_ptr; cudaGetSymbolAddress((void**)&zz_ptr, g_zz);
    float* ee_ptr; cudaGetSymbolAddress((void**)&ee_ptr, g_ee);

    vq_init_kernel<<<NROWS / 256, 256>>>();
    vq_norms_kernel<<<(NROWS * 32) / 256, 256>>>(z, zz_ptr, NROWS);
    vq_norms_kernel<<<(KCODES * 32) / 256, 256>>>(cb, ee_ptr, KCODES);
    vq_prep_z<<<512, 256>>>(z);
    vq_prep_cb<<<512, 256>>>(cb);
    vq_argmin_kernel<<<148, NTHR, SM_TOTAL>>>();
    vq_output_kernel<<<QSIZE / 1024, 256>>>(z, cb, out);
    vq_loss_kernel<<<1, 256>>>(out, out_size);
}